// round 1
// baseline (speedup 1.0000x reference)
#include <cuda_runtime.h>
#include <cstdint>

#define NROWS 8192
#define DIN   512
#define DOUT  512

#define BM 128
#define BN 128
#define BK 16
#define BKP 20   // padded k-stride (conflict-free fragment loads)

// Scratch (allocation-free): degree^-1/2 vector and intermediate support matrix.
__device__ float g_deg[NROWS];
__device__ float g_support[(size_t)NROWS * DIN];

__device__ __forceinline__ uint32_t f2tf32(float f) {
    uint32_t u;
    asm("cvt.rna.tf32.f32 %0, %1;" : "=r"(u) : "f"(f));
    return u;
}

#define MMA_TF32(d, a, b0, b1)                                                  \
    asm volatile(                                                               \
        "mma.sync.aligned.m16n8k8.row.col.f32.tf32.tf32.f32 "                   \
        "{%0,%1,%2,%3}, {%4,%5,%6,%7}, {%8,%9}, {%0,%1,%2,%3};"                 \
        : "+f"((d)[0]), "+f"((d)[1]), "+f"((d)[2]), "+f"((d)[3])                \
        : "r"((a)[0]), "r"((a)[1]), "r"((a)[2]), "r"((a)[3]),                   \
          "r"(b0), "r"(b1))

// ---------------------------------------------------------------------------
// Kernel 1: d[i] = rsqrt(1 + sum_j adj[i][j])   (one block per row)
// ---------------------------------------------------------------------------
__global__ __launch_bounds__(256) void rowsum_kernel(const float* __restrict__ adj) {
    const int row = blockIdx.x;
    const float4* p = reinterpret_cast<const float4*>(adj + (size_t)row * NROWS);
    float s = 0.f;
    for (int i = threadIdx.x; i < NROWS / 4; i += 256) {
        float4 v = p[i];
        s += (v.x + v.y) + (v.z + v.w);
    }
#pragma unroll
    for (int o = 16; o > 0; o >>= 1) s += __shfl_xor_sync(0xffffffffu, s, o);
    __shared__ float ws[8];
    if ((threadIdx.x & 31) == 0) ws[threadIdx.x >> 5] = s;
    __syncthreads();
    if (threadIdx.x == 0) {
        float t = 0.f;
#pragma unroll
        for (int i = 0; i < 8; i++) t += ws[i];
        g_deg[row] = rsqrtf(1.0f + t);
    }
}

// ---------------------------------------------------------------------------
// Kernel 2: support = d_i * ( adj @ (d_j * x_j) + d_i * x_i )
//   M = 8192 (rows of adj), N = 512 (feature dim), K = 8192
//   tf32 mma.sync, 128x128x16 CTA tile, double-buffered smem
// ---------------------------------------------------------------------------
__global__ __launch_bounds__(256, 2) void gemm1_kernel(const float* __restrict__ adj,
                                                       const float* __restrict__ x) {
    __shared__ __align__(16) uint32_t As[2][BM][BKP];
    __shared__ __align__(16) uint32_t Bs[2][BN][BKP];

    const int t  = threadIdx.x;
    const int m0 = (blockIdx.x >> 2) * BM;  // m-major ordering: col-blocks of the
    const int n0 = (blockIdx.x & 3) * BN;   // same adj rows are schedule-adjacent
    const int wid = t >> 5, lane = t & 31;
    const int g = lane >> 2, tg = lane & 3;
    const int wm = (wid & 3) * 32;
    const int wn = (wid >> 2) * 64;

    // B-tile loader mapping: one smem column (n) per thread, 8 k's
    const int bn  = t & 127;
    const int bkh = (t >> 7) * 8;

    float acc[2][8][4];
#pragma unroll
    for (int a = 0; a < 2; a++)
#pragma unroll
        for (int b = 0; b < 8; b++)
#pragma unroll
            for (int c = 0; c < 4; c++) acc[a][b][c] = 0.f;

    // ---- preload tile k0 = 0 ----
    {
#pragma unroll
        for (int i = 0; i < 2; i++) {
            int idx = t + i * 256;
            int r = idx >> 2, c4 = (idx & 3) * 4;
            float4 v = *reinterpret_cast<const float4*>(&adj[(size_t)(m0 + r) * NROWS + c4]);
            uint4 u = make_uint4(f2tf32(v.x), f2tf32(v.y), f2tf32(v.z), f2tf32(v.w));
            *reinterpret_cast<uint4*>(&As[0][r][c4]) = u;
        }
#pragma unroll
        for (int kk = 0; kk < 8; kk++) {
            int k = bkh + kk;
            float dv = g_deg[k];
            float v  = x[(size_t)k * DIN + n0 + bn];
            Bs[0][bn][k] = f2tf32(v * dv);
        }
    }
    __syncthreads();

    int buf = 0;
    for (int k0 = 0; k0 < NROWS; k0 += BK) {
        const bool has_next = (k0 + BK) < NROWS;
        float4 ra[2];
        float  rb[8], rd[8];
        int arr[2], ac4[2];
        if (has_next) {
            const int kn = k0 + BK;
#pragma unroll
            for (int i = 0; i < 2; i++) {
                int idx = t + i * 256;
                int r = idx >> 2, c4 = (idx & 3) * 4;
                arr[i] = r; ac4[i] = c4;
                ra[i] = *reinterpret_cast<const float4*>(&adj[(size_t)(m0 + r) * NROWS + kn + c4]);
            }
#pragma unroll
            for (int kk = 0; kk < 8; kk++) {
                int k = kn + bkh + kk;
                rd[kk] = g_deg[k];
                rb[kk] = x[(size_t)k * DIN + n0 + bn];
            }
        }
        // ---- compute on current buffer ----
#pragma unroll
        for (int ks = 0; ks < 2; ks++) {
            const int kb = ks * 8;
            uint32_t a[2][4];
#pragma unroll
            for (int mt = 0; mt < 2; mt++) {
                int r = wm + mt * 16;
                a[mt][0] = As[buf][r + g    ][kb + tg];
                a[mt][1] = As[buf][r + g + 8][kb + tg];
                a[mt][2] = As[buf][r + g    ][kb + tg + 4];
                a[mt][3] = As[buf][r + g + 8][kb + tg + 4];
            }
#pragma unroll
            for (int nt = 0; nt < 8; nt++) {
                uint32_t b0 = Bs[buf][wn + nt * 8 + g][kb + tg];
                uint32_t b1 = Bs[buf][wn + nt * 8 + g][kb + tg + 4];
                MMA_TF32(acc[0][nt], a[0], b0, b1);
                MMA_TF32(acc[1][nt], a[1], b0, b1);
            }
        }
        if (has_next) {
            const int nb = buf ^ 1;
#pragma unroll
            for (int i = 0; i < 2; i++) {
                uint4 u = make_uint4(f2tf32(ra[i].x), f2tf32(ra[i].y),
                                     f2tf32(ra[i].z), f2tf32(ra[i].w));
                *reinterpret_cast<uint4*>(&As[nb][arr[i]][ac4[i]]) = u;
            }
#pragma unroll
            for (int kk = 0; kk < 8; kk++) {
                Bs[nb][bn][bkh + kk] = f2tf32(rb[kk] * rd[kk]);
            }
            __syncthreads();
            buf = nb;
        }
    }

    // ---- epilogue: support = d_i*(acc + d_i*x_i) ----
#pragma unroll
    for (int mt = 0; mt < 2; mt++) {
#pragma unroll
        for (int h = 0; h < 2; h++) {
            const int grow = m0 + wm + mt * 16 + g + 8 * h;
            const float di = g_deg[grow];
#pragma unroll
            for (int nt = 0; nt < 8; nt++) {
                const int col = n0 + wn + nt * 8 + 2 * tg;
                float2 xv = *reinterpret_cast<const float2*>(&x[(size_t)grow * DIN + col]);
                float2 o;
                o.x = di * (acc[mt][nt][h * 2 + 0] + di * xv.x);
                o.y = di * (acc[mt][nt][h * 2 + 1] + di * xv.y);
                *reinterpret_cast<float2*>(&g_support[(size_t)grow * DIN + col]) = o;
            }
        }
    }
}

// ---------------------------------------------------------------------------
// Kernel 3: out = relu(support @ W^T + b)
//   M = 8192, N = 512, K = 512.  B[k][n] = W[n][k] -> Bs[n][k] = W row n.
// ---------------------------------------------------------------------------
__global__ __launch_bounds__(256, 2) void gemm2_kernel(const float* __restrict__ W,
                                                       const float* __restrict__ bias,
                                                       float* __restrict__ out) {
    __shared__ __align__(16) uint32_t As[2][BM][BKP];
    __shared__ __align__(16) uint32_t Bs[2][BN][BKP];

    const int t  = threadIdx.x;
    const int m0 = (blockIdx.x >> 2) * BM;
    const int n0 = (blockIdx.x & 3) * BN;
    const int wid = t >> 5, lane = t & 31;
    const int g = lane >> 2, tg = lane & 3;
    const int wm = (wid & 3) * 32;
    const int wn = (wid >> 2) * 64;

    float acc[2][8][4];
#pragma unroll
    for (int a = 0; a < 2; a++)
#pragma unroll
        for (int b = 0; b < 8; b++)
#pragma unroll
            for (int c = 0; c < 4; c++) acc[a][b][c] = 0.f;

    // ---- preload tile k0 = 0 ----
    {
#pragma unroll
        for (int i = 0; i < 2; i++) {
            int idx = t + i * 256;
            int r = idx >> 2, c4 = (idx & 3) * 4;
            float4 v = *reinterpret_cast<const float4*>(&g_support[(size_t)(m0 + r) * DIN + c4]);
            uint4 u = make_uint4(f2tf32(v.x), f2tf32(v.y), f2tf32(v.z), f2tf32(v.w));
            *reinterpret_cast<uint4*>(&As[0][r][c4]) = u;
            // B: Bs[n][k] = W[n0+n][k]
            float4 w = *reinterpret_cast<const float4*>(&W[(size_t)(n0 + r) * DIN + c4]);
            uint4 uw = make_uint4(f2tf32(w.x), f2tf32(w.y), f2tf32(w.z), f2tf32(w.w));
            *reinterpret_cast<uint4*>(&Bs[0][r][c4]) = uw;
        }
    }
    __syncthreads();

    int buf = 0;
    for (int k0 = 0; k0 < DIN; k0 += BK) {
        const bool has_next = (k0 + BK) < DIN;
        float4 ra[2], rw[2];
        int arr[2], ac4[2];
        if (has_next) {
            const int kn = k0 + BK;
#pragma unroll
            for (int i = 0; i < 2; i++) {
                int idx = t + i * 256;
                int r = idx >> 2, c4 = (idx & 3) * 4;
                arr[i] = r; ac4[i] = c4;
                ra[i] = *reinterpret_cast<const float4*>(&g_support[(size_t)(m0 + r) * DIN + kn + c4]);
                rw[i] = *reinterpret_cast<const float4*>(&W[(size_t)(n0 + r) * DIN + kn + c4]);
            }
        }
#pragma unroll
        for (int ks = 0; ks < 2; ks++) {
            const int kb = ks * 8;
            uint32_t a[2][4];
#pragma unroll
            for (int mt = 0; mt < 2; mt++) {
                int r = wm + mt * 16;
                a[mt][0] = As[buf][r + g    ][kb + tg];
                a[mt][1] = As[buf][r + g + 8][kb + tg];
                a[mt][2] = As[buf][r + g    ][kb + tg + 4];
                a[mt][3] = As[buf][r + g + 8][kb + tg + 4];
            }
#pragma unroll
            for (int nt = 0; nt < 8; nt++) {
                uint32_t b0 = Bs[buf][wn + nt * 8 + g][kb + tg];
                uint32_t b1 = Bs[buf][wn + nt * 8 + g][kb + tg + 4];
                MMA_TF32(acc[0][nt], a[0], b0, b1);
                MMA_TF32(acc[1][nt], a[1], b0, b1);
            }
        }
        if (has_next) {
            const int nb = buf ^ 1;
#pragma unroll
            for (int i = 0; i < 2; i++) {
                uint4 u = make_uint4(f2tf32(ra[i].x), f2tf32(ra[i].y),
                                     f2tf32(ra[i].z), f2tf32(ra[i].w));
                *reinterpret_cast<uint4*>(&As[nb][arr[i]][ac4[i]]) = u;
                uint4 uw = make_uint4(f2tf32(rw[i].x), f2tf32(rw[i].y),
                                      f2tf32(rw[i].z), f2tf32(rw[i].w));
                *reinterpret_cast<uint4*>(&Bs[nb][arr[i]][ac4[i]]) = uw;
            }
            __syncthreads();
            buf = nb;
        }
    }

    // ---- epilogue: out = relu(acc + bias) ----
#pragma unroll
    for (int mt = 0; mt < 2; mt++) {
#pragma unroll
        for (int h = 0; h < 2; h++) {
            const int grow = m0 + wm + mt * 16 + g + 8 * h;
#pragma unroll
            for (int nt = 0; nt < 8; nt++) {
                const int col = n0 + wn + nt * 8 + 2 * tg;
                float2 bv = *reinterpret_cast<const float2*>(&bias[col]);
                float2 o;
                o.x = fmaxf(acc[mt][nt][h * 2 + 0] + bv.x, 0.f);
                o.y = fmaxf(acc[mt][nt][h * 2 + 1] + bv.y, 0.f);
                *reinterpret_cast<float2*>(&out[(size_t)grow * DOUT + col]) = o;
            }
        }
    }
}

// ---------------------------------------------------------------------------
extern "C" void kernel_launch(void* const* d_in, const int* in_sizes, int n_in,
                              void* d_out, int out_size) {
    const float* x = nullptr;
    const float* adj = nullptr;
    const float* W = nullptr;
    const float* b = nullptr;
    for (int i = 0; i < n_in; i++) {
        long sz = (long)in_sizes[i];
        if (sz == (long)NROWS * NROWS)      adj = (const float*)d_in[i];
        else if (sz == (long)NROWS * DIN)   x   = (const float*)d_in[i];
        else if (sz == (long)DIN * DOUT)    W   = (const float*)d_in[i];
        else if (sz == (long)DOUT)          b   = (const float*)d_in[i];
    }
    float* out = (float*)d_out;

    rowsum_kernel<<<NROWS, 256>>>(adj);
    gemm1_kernel<<<(NROWS / BM) * (DIN / BN), 256>>>(adj, x);
    gemm2_kernel<<<(NROWS / BM) * (DOUT / BN), 256>>>(W, b, out);
}

// round 3
// speedup vs baseline: 2.0703x; 2.0703x over previous
#include <cuda_runtime.h>
#include <cuda_fp16.h>
#include <cstdint>

#define NROWS 8192
#define DIN   512
#define DOUT  512

// ---------------- fp16 mma.sync gemm tiling ----------------
#define CTAM 128
#define CTAN 256
#define CTAK 32
#define NSTAGE 4
#define ROWB 80                     // padded row stride in bytes (32 halves data + pad)
#define ABYTES (CTAM * ROWB)        // 10240
#define BBYTES (CTAN * ROWB)        // 20480
#define STAGEB (ABYTES + BBYTES)    // 30720
#define DYN_SMEM (STAGEB * NSTAGE)  // 122880

#define NT1 (NROWS / CTAK)          // 256 k-tiles for gemm1
#define NT2 (DIN / CTAK)            // 16 k-tiles for gemm2

// Scratch (allocation-free)
__device__ __half g_adj_h[(size_t)NROWS * NROWS];    // fp16 adjacency
__device__ float  g_deg[NROWS];
__device__ __half g_xsT[(size_t)DIN * NROWS];        // xsT[n][k] = half(d_k * x[k][n])
__device__ __half g_support[(size_t)NROWS * DIN];    // fp16 intermediate
__device__ __half g_Wh[(size_t)DOUT * DIN];          // fp16 weights [n][k]

// ======================= PTX helpers =======================
__device__ __forceinline__ uint32_t smem_u32(const void* p) {
    uint32_t a;
    asm("{ .reg .u64 t; cvta.to.shared.u64 t, %1; cvt.u32.u64 %0, t; }" : "=r"(a) : "l"(p));
    return a;
}

#define CP_ASYNC16(dst, src) \
    asm volatile("cp.async.cg.shared.global [%0], [%1], 16;" :: "r"(dst), "l"(src))
#define CP_COMMIT() asm volatile("cp.async.commit_group;" ::: "memory")
#define CP_WAIT2()  asm volatile("cp.async.wait_group 2;" ::: "memory")
#define CP_WAIT0()  asm volatile("cp.async.wait_group 0;" ::: "memory")

#define LDSM4(r0, r1, r2, r3, addr)                                             \
    asm volatile("ldmatrix.sync.aligned.m8n8.x4.shared.b16 {%0,%1,%2,%3}, [%4];"\
                 : "=r"(r0), "=r"(r1), "=r"(r2), "=r"(r3) : "r"(addr))

#define MMA_F16(d, a, b0, b1)                                                   \
    asm volatile(                                                               \
        "mma.sync.aligned.m16n8k16.row.col.f32.f16.f16.f32 "                    \
        "{%0,%1,%2,%3}, {%4,%5,%6,%7}, {%8,%9}, {%0,%1,%2,%3};"                 \
        : "+f"((d)[0]), "+f"((d)[1]), "+f"((d)[2]), "+f"((d)[3])                \
        : "r"((a)[0]), "r"((a)[1]), "r"((a)[2]), "r"((a)[3]),                   \
          "r"(b0), "r"(b1))

// ---------------------------------------------------------------------------
// Kernel 1: d[i] = rsqrt(1 + sum_j adj[i][j])  AND  g_adj_h = half(adj)
// ---------------------------------------------------------------------------
__global__ __launch_bounds__(256) void rowsum_convert(const float* __restrict__ adj) {
    const int row = blockIdx.x;
    const float4* p = reinterpret_cast<const float4*>(adj + (size_t)row * NROWS);
    __half2* dst = reinterpret_cast<__half2*>(g_adj_h + (size_t)row * NROWS);
    float s = 0.f;
    for (int i = threadIdx.x; i < NROWS / 4; i += 256) {
        float4 v = p[i];
        s += (v.x + v.y) + (v.z + v.w);
        dst[2 * i + 0] = __floats2half2_rn(v.x, v.y);
        dst[2 * i + 1] = __floats2half2_rn(v.z, v.w);
    }
#pragma unroll
    for (int o = 16; o > 0; o >>= 1) s += __shfl_xor_sync(0xffffffffu, s, o);
    __shared__ float ws[8];
    if ((threadIdx.x & 31) == 0) ws[threadIdx.x >> 5] = s;
    __syncthreads();
    if (threadIdx.x == 0) {
        float t = 0.f;
#pragma unroll
        for (int i = 0; i < 8; i++) t += ws[i];
        g_deg[row] = rsqrtf(1.0f + t);
    }
}

// ---------------------------------------------------------------------------
// Kernel 2: xsT[n][k] = half( d_k * x[k][n] )   (scaled transpose)
// ---------------------------------------------------------------------------
__global__ __launch_bounds__(256) void scale_transpose_h(const float* __restrict__ x) {
    __shared__ float tile[32][33];
    const int kb = blockIdx.x * 32;
    const int nb = blockIdx.y * 32;
    const int tx = threadIdx.x & 31;
    const int ty = threadIdx.x >> 5;
#pragma unroll
    for (int i = 0; i < 32; i += 8) {
        int k = kb + ty + i;
        tile[ty + i][tx] = g_deg[k] * x[(size_t)k * DIN + nb + tx];
    }
    __syncthreads();
#pragma unroll
    for (int i = 0; i < 32; i += 8) {
        int n = nb + ty + i;
        g_xsT[(size_t)n * NROWS + kb + tx] = __float2half_rn(tile[tx][ty + i]);
    }
}

// ---------------------------------------------------------------------------
// Kernel 3: W fp32 -> fp16
// ---------------------------------------------------------------------------
__global__ __launch_bounds__(256) void w_convert(const float* __restrict__ W) {
    const int i = blockIdx.x * 256 + threadIdx.x;   // 65536 threads, 4 floats each
    float4 v = reinterpret_cast<const float4*>(W)[i];
    __half2* d = reinterpret_cast<__half2*>(g_Wh) + 2 * i;
    d[0] = __floats2half2_rn(v.x, v.y);
    d[1] = __floats2half2_rn(v.z, v.w);
}

// ===========================================================================
// Shared gemm machinery: CTA 128x256, 8 warps (2m x 4n) of 64x64, BK=32,
// 4-stage cp.async, ldmatrix fragments, fp16 inputs / fp32 accum.
// ===========================================================================
struct GemmCore {
    uint32_t sbase;      // dyn smem base
    int m0, n0, wm, wn, lane;
    uint32_t aoff, boff; // per-lane ldmatrix offsets
};

__device__ __forceinline__ void core_init(GemmCore& c, char* dyn, int bid) {
    const int tid = threadIdx.x;
    const int wid = tid >> 5;
    c.lane = tid & 31;
    c.m0 = (bid >> 1) * CTAM;
    c.n0 = (bid & 1) * CTAN;
    c.wm = (wid & 1) * 64;
    c.wn = (wid >> 1) * 64;
    c.sbase = smem_u32(dyn);
    const int l = c.lane;
    c.aoff = (uint32_t)((l & 15) * ROWB + ((l >> 4) & 1) * 16);
    c.boff = (uint32_t)(((l & 7) + ((l >> 4) & 1) * 8) * ROWB + ((l >> 3) & 1) * 16);
}

// Load one k-tile into stage s via cp.async (A: strideA halves, B: strideB halves)
__device__ __forceinline__ void load_tile(const GemmCore& c,
                                          const __half* __restrict__ Ag, int strideA,
                                          const __half* __restrict__ Bg, int strideB,
                                          int t) {
    const int tid = threadIdx.x;
    const int k0 = t * CTAK;
    const uint32_t stA = c.sbase + (uint32_t)(t & (NSTAGE - 1)) * STAGEB;
    const uint32_t stB = stA + ABYTES;
#pragma unroll
    for (int i = 0; i < 2; i++) {
        int ch = tid + i * 256;
        int r = ch >> 2, q = ch & 3;
        CP_ASYNC16(stA + (uint32_t)(r * ROWB + q * 16),
                   Ag + (size_t)(c.m0 + r) * strideA + k0 + q * 8);
    }
#pragma unroll
    for (int i = 0; i < 4; i++) {
        int ch = tid + i * 256;
        int r = ch >> 2, q = ch & 3;
        CP_ASYNC16(stB + (uint32_t)(r * ROWB + q * 16),
                   Bg + (size_t)(c.n0 + r) * strideB + k0 + q * 8);
    }
}

__device__ __forceinline__ void compute_tile(const GemmCore& c, int t,
                                             float acc[4][8][4]) {
    const uint32_t stA = c.sbase + (uint32_t)(t & (NSTAGE - 1)) * STAGEB;
    const uint32_t stB = stA + ABYTES;
#pragma unroll
    for (int s = 0; s < 2; s++) {
        uint32_t a[4][4];
#pragma unroll
        for (int i = 0; i < 4; i++) {
            LDSM4(a[i][0], a[i][1], a[i][2], a[i][3],
                  stA + (uint32_t)((c.wm + 16 * i) * ROWB + s * 32) + c.aoff);
        }
        uint32_t b[8][2];
#pragma unroll
        for (int jp = 0; jp < 4; jp++) {
            LDSM4(b[2 * jp][0], b[2 * jp][1], b[2 * jp + 1][0], b[2 * jp + 1][1],
                  stB + (uint32_t)((c.wn + 16 * jp) * ROWB + s * 32) + c.boff);
        }
#pragma unroll
        for (int i = 0; i < 4; i++)
#pragma unroll
            for (int j = 0; j < 8; j++)
                MMA_F16(acc[i][j], a[i], b[j][0], b[j][1]);
    }
}

// ---------------------------------------------------------------------------
// Kernel 4: support = d_i * ( adj_h @ xsT^T + d_i * x_i )   -> fp16
// ---------------------------------------------------------------------------
__global__ __launch_bounds__(256, 1) void gemm1_h(const float* __restrict__ x) {
    extern __shared__ __align__(128) char dyn[];
    GemmCore c;
    core_init(c, dyn, blockIdx.x);

    float acc[4][8][4];
#pragma unroll
    for (int i = 0; i < 4; i++)
#pragma unroll
        for (int j = 0; j < 8; j++)
#pragma unroll
            for (int q = 0; q < 4; q++) acc[i][j][q] = 0.f;

#pragma unroll
    for (int s = 0; s < NSTAGE - 1; s++) {
        load_tile(c, g_adj_h, NROWS, g_xsT, NROWS, s);
        CP_COMMIT();
    }

    for (int t = 0; t < NT1; t++) {
        CP_WAIT2();
        __syncthreads();
        if (t + NSTAGE - 1 < NT1)
            load_tile(c, g_adj_h, NROWS, g_xsT, NROWS, t + NSTAGE - 1);
        CP_COMMIT();
        compute_tile(c, t, acc);
    }

    // epilogue: support = half( d_m * (acc + d_m * x) )
    const int g = c.lane >> 2, tg = c.lane & 3;
#pragma unroll
    for (int i = 0; i < 4; i++) {
        const int r0 = c.m0 + c.wm + 16 * i + g;
        const int r1 = r0 + 8;
        const float d0 = g_deg[r0], d1 = g_deg[r1];
#pragma unroll
        for (int j = 0; j < 8; j++) {
            const int col = c.n0 + c.wn + 8 * j + 2 * tg;
            float2 x0 = *reinterpret_cast<const float2*>(&x[(size_t)r0 * DIN + col]);
            float2 x1 = *reinterpret_cast<const float2*>(&x[(size_t)r1 * DIN + col]);
            __half2 h0 = __floats2half2_rn(d0 * (acc[i][j][0] + d0 * x0.x),
                                           d0 * (acc[i][j][1] + d0 * x0.y));
            __half2 h1 = __floats2half2_rn(d1 * (acc[i][j][2] + d1 * x1.x),
                                           d1 * (acc[i][j][3] + d1 * x1.y));
            *reinterpret_cast<__half2*>(&g_support[(size_t)r0 * DIN + col]) = h0;
            *reinterpret_cast<__half2*>(&g_support[(size_t)r1 * DIN + col]) = h1;
        }
    }
}

// ---------------------------------------------------------------------------
// Kernel 5: out = relu(support @ Wh^T + b)   -> fp32
// ---------------------------------------------------------------------------
__global__ __launch_bounds__(256, 1) void gemm2_h(const float* __restrict__ bias,
                                                  float* __restrict__ out) {
    extern __shared__ __align__(128) char dyn[];
    GemmCore c;
    core_init(c, dyn, blockIdx.x);

    float acc[4][8][4];
#pragma unroll
    for (int i = 0; i < 4; i++)
#pragma unroll
        for (int j = 0; j < 8; j++)
#pragma unroll
            for (int q = 0; q < 4; q++) acc[i][j][q] = 0.f;

#pragma unroll
    for (int s = 0; s < NSTAGE - 1; s++) {
        load_tile(c, g_support, DIN, g_Wh, DIN, s);
        CP_COMMIT();
    }

    for (int t = 0; t < NT2; t++) {
        CP_WAIT2();
        __syncthreads();
        if (t + NSTAGE - 1 < NT2)
            load_tile(c, g_support, DIN, g_Wh, DIN, t + NSTAGE - 1);
        CP_COMMIT();
        compute_tile(c, t, acc);
    }

    const int g = c.lane >> 2, tg = c.lane & 3;
#pragma unroll
    for (int i = 0; i < 4; i++) {
        const int r0 = c.m0 + c.wm + 16 * i + g;
        const int r1 = r0 + 8;
#pragma unroll
        for (int j = 0; j < 8; j++) {
            const int col = c.n0 + c.wn + 8 * j + 2 * tg;
            float2 bv = *reinterpret_cast<const float2*>(&bias[col]);
            float2 o0, o1;
            o0.x = fmaxf(acc[i][j][0] + bv.x, 0.f);
            o0.y = fmaxf(acc[i][j][1] + bv.y, 0.f);
            o1.x = fmaxf(acc[i][j][2] + bv.x, 0.f);
            o1.y = fmaxf(acc[i][j][3] + bv.y, 0.f);
            *reinterpret_cast<float2*>(&out[(size_t)r0 * DOUT + col]) = o0;
            *reinterpret_cast<float2*>(&out[(size_t)r1 * DOUT + col]) = o1;
        }
    }
}

// ---------------------------------------------------------------------------
extern "C" void kernel_launch(void* const* d_in, const int* in_sizes, int n_in,
                              void* d_out, int out_size) {
    const float* x = nullptr;
    const float* adj = nullptr;
    const float* W = nullptr;
    const float* b = nullptr;
    for (int i = 0; i < n_in; i++) {
        long sz = (long)in_sizes[i];
        if (sz == (long)NROWS * NROWS)      adj = (const float*)d_in[i];
        else if (sz == (long)NROWS * DIN)   x   = (const float*)d_in[i];
        else if (sz == (long)DIN * DOUT)    W   = (const float*)d_in[i];
        else if (sz == (long)DOUT)          b   = (const float*)d_in[i];
    }
    float* out = (float*)d_out;

    static bool attr_done = false;
    if (!attr_done) {
        cudaFuncSetAttribute(gemm1_h, cudaFuncAttributeMaxDynamicSharedMemorySize, DYN_SMEM);
        cudaFuncSetAttribute(gemm2_h, cudaFuncAttributeMaxDynamicSharedMemorySize, DYN_SMEM);
        attr_done = true;
    }

    rowsum_convert<<<NROWS, 256>>>(adj);
    scale_transpose_h<<<dim3(NROWS / 32, DIN / 32), 256>>>(x);
    w_convert<<<(DOUT * DIN / 4) / 256, 256>>>(W);
    gemm1_h<<<(NROWS / CTAM) * (DIN / CTAN), 256, DYN_SMEM>>>(x);
    gemm2_h<<<(NROWS / CTAM) * (DOUT / CTAN), 256, DYN_SMEM>>>(b, out);
}

// round 4
// speedup vs baseline: 2.8360x; 1.3698x over previous
#include <cuda_runtime.h>
#include <cuda_fp16.h>
#include <cstdint>

#define NROWS 8192
#define DIN   512
#define DOUT  512

// ---------------- fp16 mma.sync gemm tiling ----------------
#define CTAM 128
#define CTAN 256
#define CTAK 32
#define NSTAGE 4
#define ROWB 80                     // padded row stride in bytes (32 halves data + pad)
#define ABYTES (CTAM * ROWB)        // 10240
#define BBYTES (CTAN * ROWB)        // 20480
#define STAGEB (ABYTES + BBYTES)    // 30720
#define DYN_SMEM (STAGEB * NSTAGE)  // 122880

#define NT1 (NROWS / CTAK)          // 256 k-tiles for gemm1
#define NT2 (DIN / CTAK)            // 16 k-tiles for gemm2

// Scratch (allocation-free)
__device__ __half g_adj_h[(size_t)NROWS * NROWS];    // fp16 adjacency
__device__ float  g_deg[NROWS];
__device__ __half g_xsT[(size_t)DIN * NROWS];        // xsT[n][k] = half(d_k * x[k][n])
__device__ __half g_support[(size_t)NROWS * DIN];    // fp16 intermediate
__device__ __half g_Wh[(size_t)DOUT * DIN];          // fp16 weights [n][k]

// ======================= PTX helpers =======================
__device__ __forceinline__ uint32_t smem_u32(const void* p) {
    uint32_t a;
    asm("{ .reg .u64 t; cvta.to.shared.u64 t, %1; cvt.u32.u64 %0, t; }" : "=r"(a) : "l"(p));
    return a;
}

#define CP_ASYNC16(dst, src) \
    asm volatile("cp.async.cg.shared.global [%0], [%1], 16;" :: "r"(dst), "l"(src))
#define CP_COMMIT() asm volatile("cp.async.commit_group;" ::: "memory")
#define CP_WAITG2() asm volatile("cp.async.wait_group 2;" ::: "memory")

#define LDSM4(r0, r1, r2, r3, addr)                                             \
    asm volatile("ldmatrix.sync.aligned.m8n8.x4.shared.b16 {%0,%1,%2,%3}, [%4];"\
                 : "=r"(r0), "=r"(r1), "=r"(r2), "=r"(r3) : "r"(addr))

#define MMA_F16(d, a, b0, b1)                                                   \
    asm volatile(                                                               \
        "mma.sync.aligned.m16n8k16.row.col.f32.f16.f16.f32 "                    \
        "{%0,%1,%2,%3}, {%4,%5,%6,%7}, {%8,%9}, {%0,%1,%2,%3};"                 \
        : "+f"((d)[0]), "+f"((d)[1]), "+f"((d)[2]), "+f"((d)[3])                \
        : "r"((a)[0]), "r"((a)[1]), "r"((a)[2]), "r"((a)[3]),                   \
          "r"(b0), "r"(b1))

// ---------------------------------------------------------------------------
// Kernel 1: d[i] = rsqrt(1 + sum_j adj[i][j])  AND  g_adj_h = half(adj)
// ---------------------------------------------------------------------------
__global__ __launch_bounds__(256) void rowsum_convert(const float* __restrict__ adj) {
    const int row = blockIdx.x;
    const float4* p = reinterpret_cast<const float4*>(adj + (size_t)row * NROWS);
    __half2* dst = reinterpret_cast<__half2*>(g_adj_h + (size_t)row * NROWS);
    float s = 0.f;
    for (int i = threadIdx.x; i < NROWS / 4; i += 256) {
        float4 v = p[i];
        s += (v.x + v.y) + (v.z + v.w);
        dst[2 * i + 0] = __floats2half2_rn(v.x, v.y);
        dst[2 * i + 1] = __floats2half2_rn(v.z, v.w);
    }
#pragma unroll
    for (int o = 16; o > 0; o >>= 1) s += __shfl_xor_sync(0xffffffffu, s, o);
    __shared__ float ws[8];
    if ((threadIdx.x & 31) == 0) ws[threadIdx.x >> 5] = s;
    __syncthreads();
    if (threadIdx.x == 0) {
        float t = 0.f;
#pragma unroll
        for (int i = 0; i < 8; i++) t += ws[i];
        g_deg[row] = rsqrtf(1.0f + t);
    }
}

// ---------------------------------------------------------------------------
// Kernel 2: xsT[n][k] = half( d_k * x[k][n] )   (scaled transpose)
// ---------------------------------------------------------------------------
__global__ __launch_bounds__(256) void scale_transpose_h(const float* __restrict__ x) {
    __shared__ float tile[32][33];
    const int kb = blockIdx.x * 32;
    const int nb = blockIdx.y * 32;
    const int tx = threadIdx.x & 31;
    const int ty = threadIdx.x >> 5;
#pragma unroll
    for (int i = 0; i < 32; i += 8) {
        int k = kb + ty + i;
        tile[ty + i][tx] = g_deg[k] * x[(size_t)k * DIN + nb + tx];
    }
    __syncthreads();
#pragma unroll
    for (int i = 0; i < 32; i += 8) {
        int n = nb + ty + i;
        g_xsT[(size_t)n * NROWS + kb + tx] = __float2half_rn(tile[tx][ty + i]);
    }
}

// ---------------------------------------------------------------------------
// Kernel 3: W fp32 -> fp16
// ---------------------------------------------------------------------------
__global__ __launch_bounds__(256) void w_convert(const float* __restrict__ W) {
    const int i = blockIdx.x * 256 + threadIdx.x;
    float4 v = reinterpret_cast<const float4*>(W)[i];
    __half2* d = reinterpret_cast<__half2*>(g_Wh) + 2 * i;
    d[0] = __floats2half2_rn(v.x, v.y);
    d[1] = __floats2half2_rn(v.z, v.w);
}

// ===========================================================================
// Gemm core: CTA 128x256, 8 warps (2m x 4n) of 64x64, BK=32, 4-stage cp.async,
// double-buffered ldmatrix fragments (cross-tile software pipeline).
// ===========================================================================
struct GemmCore {
    uint32_t sbase;
    int m0, n0, wm, wn, lane;
    uint32_t aoff, boff;
};

__device__ __forceinline__ void core_init(GemmCore& c, char* dyn, int bid) {
    const int tid = threadIdx.x;
    const int wid = tid >> 5;
    c.lane = tid & 31;
    c.m0 = (bid >> 1) * CTAM;
    c.n0 = (bid & 1) * CTAN;
    c.wm = (wid & 1) * 64;
    c.wn = (wid >> 1) * 64;
    c.sbase = smem_u32(dyn);
    const int l = c.lane;
    c.aoff = (uint32_t)((l & 15) * ROWB + ((l >> 4) & 1) * 16);
    c.boff = (uint32_t)(((l & 7) + ((l >> 4) & 1) * 8) * ROWB + ((l >> 3) & 1) * 16);
}

__device__ __forceinline__ void load_tile(const GemmCore& c,
                                          const __half* __restrict__ Ag, int strideA,
                                          const __half* __restrict__ Bg, int strideB,
                                          int t) {
    const int tid = threadIdx.x;
    const int k0 = t * CTAK;
    const uint32_t stA = c.sbase + (uint32_t)(t & (NSTAGE - 1)) * STAGEB;
    const uint32_t stB = stA + ABYTES;
#pragma unroll
    for (int i = 0; i < 2; i++) {
        int ch = tid + i * 256;
        int r = ch >> 2, q = ch & 3;
        CP_ASYNC16(stA + (uint32_t)(r * ROWB + q * 16),
                   Ag + (size_t)(c.m0 + r) * strideA + k0 + q * 8);
    }
#pragma unroll
    for (int i = 0; i < 4; i++) {
        int ch = tid + i * 256;
        int r = ch >> 2, q = ch & 3;
        CP_ASYNC16(stB + (uint32_t)(r * ROWB + q * 16),
                   Bg + (size_t)(c.n0 + r) * strideB + k0 + q * 8);
    }
}

// Load all fragments for k-half s (s in {0,1}) of tile t.
__device__ __forceinline__ void lds_frags(const GemmCore& c, int t, int s,
                                          uint32_t a[4][4], uint32_t b[8][2]) {
    const uint32_t stA = c.sbase + (uint32_t)(t & (NSTAGE - 1)) * STAGEB;
    const uint32_t stB = stA + ABYTES;
#pragma unroll
    for (int i = 0; i < 4; i++)
        LDSM4(a[i][0], a[i][1], a[i][2], a[i][3],
              stA + (uint32_t)((c.wm + 16 * i) * ROWB + s * 32) + c.aoff);
#pragma unroll
    for (int jp = 0; jp < 4; jp++)
        LDSM4(b[2 * jp][0], b[2 * jp][1], b[2 * jp + 1][0], b[2 * jp + 1][1],
              stB + (uint32_t)((c.wn + 16 * jp) * ROWB + s * 32) + c.boff);
}

__device__ __forceinline__ void mma_all(float acc[4][8][4],
                                        uint32_t a[4][4], uint32_t b[8][2]) {
#pragma unroll
    for (int i = 0; i < 4; i++)
#pragma unroll
        for (int j = 0; j < 8; j++)
            MMA_F16(acc[i][j], a[i], b[j][0], b[j][1]);
}

// Pipelined mainloop shared by both gemms.
__device__ __forceinline__ void gemm_mainloop(const GemmCore& c,
                                              const __half* __restrict__ Ag, int strideA,
                                              const __half* __restrict__ Bg, int strideB,
                                              int ntiles, float acc[4][8][4]) {
    // prologue: stages 0..2
#pragma unroll
    for (int s = 0; s < NSTAGE - 1; s++) {
        load_tile(c, Ag, strideA, Bg, strideB, s);
        CP_COMMIT();
    }
    CP_WAITG2();                 // tile 0 resident
    __syncthreads();

    uint32_t a0[4][4], b0[8][2], a1[4][4], b1[8][2];
    lds_frags(c, 0, 0, a0, b0);

    for (int t = 0; t < ntiles; t++) {
        if (t + NSTAGE - 1 < ntiles)
            load_tile(c, Ag, strideA, Bg, strideB, t + NSTAGE - 1);
        CP_COMMIT();                     // uniform group count per iter
        lds_frags(c, t, 1, a1, b1);      // overlaps with mma below
        mma_all(acc, a0, b0);
        if (t + 1 < ntiles) {
            CP_WAITG2();                 // tile t+1 resident
            __syncthreads();             // stage slot (t+3)&3 safe to refill next iter
            lds_frags(c, t + 1, 0, a0, b0);  // overlaps with mma below
        }
        mma_all(acc, a1, b1);
    }
}

// ---------------------------------------------------------------------------
// Kernel 4: support = d_i * ( adj_h @ xsT^T + d_i * x_i )   -> fp16
// ---------------------------------------------------------------------------
__global__ __launch_bounds__(256, 1) void gemm1_h(const float* __restrict__ x) {
    extern __shared__ __align__(128) char dyn[];
    GemmCore c;
    core_init(c, dyn, blockIdx.x);

    float acc[4][8][4];
#pragma unroll
    for (int i = 0; i < 4; i++)
#pragma unroll
        for (int j = 0; j < 8; j++)
#pragma unroll
            for (int q = 0; q < 4; q++) acc[i][j][q] = 0.f;

    gemm_mainloop(c, g_adj_h, NROWS, g_xsT, NROWS, NT1, acc);

    // epilogue: support = half( d_m * (acc + d_m * x) )
    const int g = c.lane >> 2, tg = c.lane & 3;
#pragma unroll
    for (int i = 0; i < 4; i++) {
        const int r0 = c.m0 + c.wm + 16 * i + g;
        const int r1 = r0 + 8;
        const float d0 = g_deg[r0], d1 = g_deg[r1];
#pragma unroll
        for (int j = 0; j < 8; j++) {
            const int col = c.n0 + c.wn + 8 * j + 2 * tg;
            float2 x0 = *reinterpret_cast<const float2*>(&x[(size_t)r0 * DIN + col]);
            float2 x1 = *reinterpret_cast<const float2*>(&x[(size_t)r1 * DIN + col]);
            __half2 h0 = __floats2half2_rn(d0 * (acc[i][j][0] + d0 * x0.x),
                                           d0 * (acc[i][j][1] + d0 * x0.y));
            __half2 h1 = __floats2half2_rn(d1 * (acc[i][j][2] + d1 * x1.x),
                                           d1 * (acc[i][j][3] + d1 * x1.y));
            *reinterpret_cast<__half2*>(&g_support[(size_t)r0 * DIN + col]) = h0;
            *reinterpret_cast<__half2*>(&g_support[(size_t)r1 * DIN + col]) = h1;
        }
    }
}

// ---------------------------------------------------------------------------
// Kernel 5: out = relu(support @ Wh^T + b)   -> fp32
// ---------------------------------------------------------------------------
__global__ __launch_bounds__(256, 1) void gemm2_h(const float* __restrict__ bias,
                                                  float* __restrict__ out) {
    extern __shared__ __align__(128) char dyn[];
    GemmCore c;
    core_init(c, dyn, blockIdx.x);

    float acc[4][8][4];
#pragma unroll
    for (int i = 0; i < 4; i++)
#pragma unroll
        for (int j = 0; j < 8; j++)
#pragma unroll
            for (int q = 0; q < 4; q++) acc[i][j][q] = 0.f;

    gemm_mainloop(c, g_support, DIN, g_Wh, DIN, NT2, acc);

    const int g = c.lane >> 2, tg = c.lane & 3;
#pragma unroll
    for (int i = 0; i < 4; i++) {
        const int r0 = c.m0 + c.wm + 16 * i + g;
        const int r1 = r0 + 8;
#pragma unroll
        for (int j = 0; j < 8; j++) {
            const int col = c.n0 + c.wn + 8 * j + 2 * tg;
            float2 bv = *reinterpret_cast<const float2*>(&bias[col]);
            float2 o0, o1;
            o0.x = fmaxf(acc[i][j][0] + bv.x, 0.f);
            o0.y = fmaxf(acc[i][j][1] + bv.y, 0.f);
            o1.x = fmaxf(acc[i][j][2] + bv.x, 0.f);
            o1.y = fmaxf(acc[i][j][3] + bv.y, 0.f);
            *reinterpret_cast<float2*>(&out[(size_t)r0 * DOUT + col]) = o0;
            *reinterpret_cast<float2*>(&out[(size_t)r1 * DOUT + col]) = o1;
        }
    }
}

// ---------------------------------------------------------------------------
extern "C" void kernel_launch(void* const* d_in, const int* in_sizes, int n_in,
                              void* d_out, int out_size) {
    const float* x = nullptr;
    const float* adj = nullptr;
    const float* W = nullptr;
    const float* b = nullptr;
    for (int i = 0; i < n_in; i++) {
        long sz = (long)in_sizes[i];
        if (sz == (long)NROWS * NROWS)      adj = (const float*)d_in[i];
        else if (sz == (long)NROWS * DIN)   x   = (const float*)d_in[i];
        else if (sz == (long)DIN * DOUT)    W   = (const float*)d_in[i];
        else if (sz == (long)DOUT)          b   = (const float*)d_in[i];
    }
    float* out = (float*)d_out;

    cudaFuncSetAttribute(gemm1_h, cudaFuncAttributeMaxDynamicSharedMemorySize, DYN_SMEM);
    cudaFuncSetAttribute(gemm2_h, cudaFuncAttributeMaxDynamicSharedMemorySize, DYN_SMEM);

    rowsum_convert<<<NROWS, 256>>>(adj);
    scale_transpose_h<<<dim3(NROWS / 32, DIN / 32), 256>>>(x);
    w_convert<<<(DOUT * DIN / 4) / 256, 256>>>(W);
    gemm1_h<<<(NROWS / CTAM) * (DIN / CTAN), 256, DYN_SMEM>>>(x);
    gemm2_h<<<(NROWS / CTAM) * (DOUT / CTAN), 256, DYN_SMEM>>>(b, out);
}